// round 8
// baseline (speedup 1.0000x reference)
#include <cuda_runtime.h>
#include <math.h>

#define NATOMS 256
#define RCR 5.2f
#define RCA 3.5f
#define PI_F 3.14159265358979323846f
#define CAP_R 96   // radial neighbors (mean ~19)
#define CAP_A 48   // angular neighbors (mean ~5.7)
#define FULL 0xFFFFFFFFu
#define TPB 128    // 4 warps per atom
#define NREP (NATOMS / TPB)   // 2

__global__ void __launch_bounds__(TPB) aev_kernel(
    const float* __restrict__ coords,
    const float* __restrict__ charges,
    float* __restrict__ out)
{
    __shared__ float rd[CAP_R], rq[CAP_R];                    // radial: dist, charge
    __shared__ float adx[CAP_A], ady[CAP_A], adz[CAP_A];      // angular: i->j vector
    __shared__ float ad[CAP_A], aq[CAP_A], afq[CAP_A];        // dist, charge, fc*q
    __shared__ int   wcR[NREP * 4], wcA[NREP * 4];            // per (rep,warp) counts
    __shared__ float part[TPB][49];                           // padded transpose buffer

    const int i    = blockIdx.x;
    const int tid  = threadIdx.x;
    const int w    = tid >> 5;
    const int lane = tid & 31;
    const unsigned below = (1u << lane) - 1u;

    const float xi = __ldg(&coords[i * 3 + 0]);
    const float yi = __ldg(&coords[i * 3 + 1]);
    const float zi = __ldg(&coords[i * 3 + 2]);

    // ---------- pass 1: distances + ballots only (no transcendental math) ----------
    float dxv[NREP], dyv[NREP], dzv[NREP], dv[NREP], qv[NREP];
    unsigned mRv[NREP], mAv[NREP];
    bool inRv[NREP], inAv[NREP];

    #pragma unroll
    for (int rep = 0; rep < NREP; rep++) {
        const int j = rep * TPB + tid;
        const float dx = __ldg(&coords[j * 3 + 0]) - xi;
        const float dy = __ldg(&coords[j * 3 + 1]) - yi;
        const float dz = __ldg(&coords[j * 3 + 2]) - zi;
        const float d  = sqrtf(dx * dx + dy * dy + dz * dz);
        const bool ok  = (j != i);
        const bool inR = ok && (d < RCR);
        const bool inA = ok && (d < RCA);
        dxv[rep] = dx; dyv[rep] = dy; dzv[rep] = dz; dv[rep] = d;
        qv[rep]  = __ldg(&charges[j]);
        inRv[rep] = inR; inAv[rep] = inA;
        mRv[rep] = __ballot_sync(FULL, inR);
        mAv[rep] = __ballot_sync(FULL, inA);
        if (lane == 0) {
            wcR[rep * 4 + w] = __popc(mRv[rep]);
            wcA[rep * 4 + w] = __popc(mAv[rep]);
        }
    }
    // zero the radial rows of the transpose buffer for warps 1-3 (their accR
    // is never written); warp 0 writes its real partials later.
    if (w != 0) {
        #pragma unroll
        for (int m = 0; m < 16; m++) part[tid][m] = 0.0f;
    }
    __syncthreads();

    // ---------- pass 2: deterministic compaction (raw data only) ----------
    #pragma unroll
    for (int rep = 0; rep < NREP; rep++) {
        const int seg = rep * 4 + w;
        int baseR = 0, baseA = 0;
        #pragma unroll
        for (int k = 0; k < NREP * 4; k++)
            if (k < seg) { baseR += wcR[k]; baseA += wcA[k]; }
        if (inRv[rep]) {
            const int s = baseR + __popc(mRv[rep] & below);
            rd[s] = dv[rep]; rq[s] = qv[rep];
        }
        if (inAv[rep]) {
            const int s = baseA + __popc(mAv[rep] & below);
            adx[s] = dxv[rep]; ady[s] = dyv[rep]; adz[s] = dzv[rep];
            ad[s] = dv[rep];  aq[s] = qv[rep];
        }
    }
    __syncthreads();

    int NR = 0, NA = 0;
    #pragma unroll
    for (int k = 0; k < NREP * 4; k++) { NR += wcR[k]; NA += wcA[k]; }

    // ---------- stage 3 (warp-specialized): warp0 radial, warp1 angular cutoffs ----------
    if (w == 0) {
        float accR[16];
        #pragma unroll
        for (int m = 0; m < 16; m++) accR[m] = 0.0f;
        for (int t = lane; t < NR; t += 32) {
            const float d  = rd[t];
            const float fc = 0.5f * __cosf((PI_F / RCR) * d) + 0.5f;
            const float wq = 0.25f * fc * rq[t];
            #pragma unroll
            for (int m = 0; m < 16; m++) {
                const float sh = 0.9f + 0.26875f * (float)m;
                const float u  = d - sh;
                accR[m] += wq * __expf(-16.0f * u * u);
            }
        }
        #pragma unroll
        for (int m = 0; m < 16; m++) part[tid][m] = accR[m];
    } else if (w == 1) {
        for (int t = lane; t < NA; t += 32) {
            const float fc = 0.5f * __cosf((PI_F / RCA) * ad[t]) + 0.5f;
            afq[t] = fc * aq[t];
        }
    }
    __syncthreads();

    // ---------- angular: pair-per-lane (reversed mapping -> lands on warps 3,2,1) ----------
    float accA[32];
    #pragma unroll
    for (int s = 0; s < 32; s++) accA[s] = 0.0f;

    const int M  = NA;
    const int PP = M * M;
    const float fM = (float)M;
    for (int p = (TPB - 1) - tid; p < PP; p += TPB) {
        // float division exact enough for p < 2^12, M >= 2 (err 1/M >> ulp)
        const int a = (int)(__fdividef((float)p, fM));
        const int b = p - a * M;
        if (a >= b) continue;  // unordered pairs; reference double-counts ordered -> x2

        const float da = ad[a], db = ad[b];
        const float dot = adx[a] * adx[b] + ady[a] * ady[b] + adz[a] * adz[b];
        const float cth = 0.95f * __fdividef(dot, da * db);      // |cth| <= 0.95
        const float sth = sqrtf(fmaxf(1.0f - cth * cth, 0.0f));  // theta in [0,pi]
        const float wgt = 2.0f * afq[a] * afq[b];
        const float davg = 0.5f * (da + db);

        #pragma unroll
        for (int az = 0; az < 4; az++) {
            const float sha = 0.9f + 0.65f * (float)az;
            const float u   = davg - sha;
            const float rad = wgt * __expf(-8.0f * u * u);
            #pragma unroll
            for (int zz = 0; zz < 8; zz++) {
                const float ang = PI_F / 16.0f + (PI_F / 8.0f) * (float)zz;
                const float cz  = cosf(ang);   // compile-time constants
                const float sz  = sinf(ang);
                // cos(theta - ShfZ) = cth*cos(ShfZ) + sin(theta)*sin(ShfZ)  (exact)
                const float x   = 0.5f * (1.0f + cth * cz + sth * sz);
                const float x2  = x * x;
                const float x4  = x2 * x2;
                const float x8  = x4 * x4;
                const float x16 = x8 * x8;
                accA[az * 8 + zz] += rad * (x16 * x16);
            }
        }
    }

    // ---------- shared transpose + 8-way-ILP column sum ----------
    #pragma unroll
    for (int s = 0; s < 32; s++) part[tid][16 + s] = accA[s];
    __syncthreads();

    if (tid < 48) {
        float v0 = 0.f, v1 = 0.f, v2 = 0.f, v3 = 0.f;
        float v4 = 0.f, v5 = 0.f, v6 = 0.f, v7 = 0.f;
        #pragma unroll
        for (int l = 0; l < TPB; l += 8) {
            v0 += part[l + 0][tid];
            v1 += part[l + 1][tid];
            v2 += part[l + 2][tid];
            v3 += part[l + 3][tid];
            v4 += part[l + 4][tid];
            v5 += part[l + 5][tid];
            v6 += part[l + 6][tid];
            v7 += part[l + 7][tid];
        }
        out[i * 48 + tid] = ((v0 + v1) + (v2 + v3)) + ((v4 + v5) + (v6 + v7));
    }
}

extern "C" void kernel_launch(void* const* d_in, const int* in_sizes, int n_in,
                              void* d_out, int out_size) {
    const float* coords  = (const float*)d_in[0];  // [256,3] fp32
    const float* charges = (const float*)d_in[1];  // [256]   fp32
    float* out = (float*)d_out;                    // [256,48] fp32
    aev_kernel<<<NATOMS, TPB>>>(coords, charges, out);
}